// round 2
// baseline (speedup 1.0000x reference)
#include <cuda_runtime.h>
#include <math.h>

#define HWSZ 16384
#define CHN  256
#define KQ   1024
#define NQ   2048

// ---------------- device scratch (static, allocation-free) ----------------
__device__ float    g_val[(size_t)2 * 4 * HWSZ * CHN];   // [b*4+f][y][x][c], +time_pos
__device__ unsigned g_keys[2 * HWSZ];
__device__ int      g_ind[NQ];
__device__ float    g_q[NQ * CHN];
__device__ float    g_qpos[NQ * CHN];
__device__ float    g_attn[NQ * CHN];

__device__ __forceinline__ float gelu_tanh(float v) {
    float c = 0.7978845608028654f * (v + 0.044715f * v * v * v);
    return 0.5f * v * (1.0f + tanhf(c));
}

// ---------------- K1: transpose x[b,f,c,y,x] -> g_val[b,f,y,x,c] (+time_pos) ----------------
__global__ void k_transpose(const float* __restrict__ x, const float* __restrict__ tp) {
    __shared__ float tile[32][33];
    int xt = blockIdx.x * 32;          // x tile
    int ct = blockIdx.y * 32;          // channel tile
    int z  = blockIdx.z;               // (b*4+f)*128 + y
    int y  = z & 127;
    int bf = z >> 7;
    int f  = bf & 3;
    int tx = threadIdx.x, ty = threadIdx.y;
    tile[ty][tx] = x[((size_t)(bf * CHN + ct + ty) * 128 + y) * 128 + xt + tx];
    __syncthreads();
    g_val[((size_t)(bf * 128 + y) * 128 + xt + ty) * CHN + ct + tx] =
        tile[tx][ty] + tp[f * CHN + ct + tx];
}

// ---------------- K2: channel-max score + radix top-1024 per batch ----------------
__global__ __launch_bounds__(1024) void k_topk(const float* __restrict__ hm) {
    int b = blockIdx.x, t = threadIdx.x;
    __shared__ unsigned hist[256];
    __shared__ unsigned sh[4];
    const float* hb = hm + (size_t)b * 10 * HWSZ;

    for (int i = t; i < HWSZ; i += 1024) {
        float m = hb[i];
        #pragma unroll
        for (int c = 1; c < 10; c++) m = fmaxf(m, hb[c * HWSZ + i]);
        unsigned u = __float_as_uint(m);
        u = (u & 0x80000000u) ? ~u : (u | 0x80000000u);   // orderable key
        g_keys[b * HWSZ + i] = u;
    }
    __syncthreads();

    unsigned prefix = 0, r = KQ;
    for (int byte = 3; byte >= 0; byte--) {
        if (t < 256) hist[t] = 0;
        __syncthreads();
        int sh8 = byte * 8;
        unsigned pm = (byte == 3) ? 0u : (0xFFFFFFFFu << (8 * (byte + 1)));
        for (int i = t; i < HWSZ; i += 1024) {
            unsigned k = g_keys[b * HWSZ + i];
            if ((k & pm) == (prefix & pm)) atomicAdd(&hist[(k >> sh8) & 255u], 1u);
        }
        __syncthreads();
        if (t == 0) {
            unsigned cum = 0, d = 0;
            for (int dd = 255; dd >= 0; dd--) {
                if (cum + hist[dd] >= r) { d = (unsigned)dd; break; }
                cum += hist[dd];
            }
            sh[0] = d; sh[1] = r - cum;
        }
        __syncthreads();
        prefix |= sh[0] << sh8;
        r = sh[1];
        __syncthreads();
    }
    unsigned T = prefix;
    if (t == 0) { sh[2] = 0; sh[3] = 0; }
    __syncthreads();
    for (int i = t; i < HWSZ; i += 1024)
        if (g_keys[b * HWSZ + i] > T) atomicAdd(&sh[2], 1u);
    __syncthreads();
    unsigned cgt = sh[2];
    unsigned neq = KQ - cgt;
    __syncthreads();
    if (t == 0) sh[2] = 0;
    __syncthreads();
    for (int i = t; i < HWSZ; i += 1024) {
        unsigned k = g_keys[b * HWSZ + i];
        if (k > T) {
            unsigned s = atomicAdd(&sh[2], 1u);
            g_ind[b * KQ + s] = i;
        } else if (k == T) {
            unsigned e = atomicAdd(&sh[3], 1u);
            if (e < neq) g_ind[b * KQ + cgt + e] = i;
        }
    }
}

// ---------------- K3: query-init MLP + positional embed gather ----------------
__global__ __launch_bounds__(256) void k_qinit(
    const float* __restrict__ preds,
    const float* __restrict__ W1, const float* __restrict__ b1,
    const float* __restrict__ W2, const float* __restrict__ b2,
    const float* __restrict__ rowe, const float* __restrict__ cole) {
    __shared__ float q0S[8][70];
    __shared__ float hidS[8][CHN];
    __shared__ int   indS[8];
    int t = threadIdx.x;
    int qg0 = blockIdx.x * 8;
    if (t < 8) indS[t] = g_ind[qg0 + t];
    __syncthreads();
    for (int idx = t; idx < 8 * 70; idx += 256) {
        int q = idx / 70, j = idx - q * 70;
        int b = (qg0 + q) >> 10;
        q0S[q][j] = preds[(b * 70 + j) * HWSZ + indS[q]];
    }
    #pragma unroll
    for (int q = 0; q < 8; q++) {
        int ind = indS[q];
        int xx = ind & 127, yy = ind >> 7;
        float pv = (t < 128) ? cole[xx * 128 + t] : rowe[yy * 128 + (t - 128)];
        g_qpos[(qg0 + q) * CHN + t] = pv;
    }
    __syncthreads();
    float acc[8] = {0.f,0.f,0.f,0.f,0.f,0.f,0.f,0.f};
    for (int j = 0; j < 70; j++) {
        float w = W1[j * CHN + t];
        #pragma unroll
        for (int q = 0; q < 8; q++) acc[q] += q0S[q][j] * w;
    }
    float bb = b1[t];
    #pragma unroll
    for (int q = 0; q < 8; q++) hidS[q][t] = gelu_tanh(acc[q] + bb);
    __syncthreads();
    float a2[8] = {0.f,0.f,0.f,0.f,0.f,0.f,0.f,0.f};
    for (int i = 0; i < CHN; i++) {
        float w = W2[i * CHN + t];
        #pragma unroll
        for (int q = 0; q < 8; q++) a2[q] += hidS[q][i] * w;
    }
    float b2v = b2[t];
    #pragma unroll
    for (int q = 0; q < 8; q++) g_q[(qg0 + q) * CHN + t] = a2[q] + b2v;
}

// ---------------- K4: per-layer sampling attention ----------------
// so/aw GEMM + softmax + gather-aggregate (GEMM commuted past sampling) + vp projection
__global__ __launch_bounds__(256) void k_sample(
    const float* __restrict__ soW, const float* __restrict__ sob,
    const float* __restrict__ awW, const float* __restrict__ awb,
    const float* __restrict__ vpW, const float* __restrict__ vpb) {
    __shared__ float aggS[4 * 8 * CHN];   // 32KB  [q][h][ch]; first 4KB aliased as qnS
    __shared__ float soS[4 * CHN];        // 4KB
    __shared__ float awS[4 * 128];        // 2KB
    __shared__ float coefS[512];          // 2KB (one q at a time)
    __shared__ int   offS[512];           // 2KB
    __shared__ float bwAll[32];           // [q][h]
    float* qnS = aggS;                    // alias: dead before aggS writes begin

    int t = threadIdx.x;
    int qg0 = blockIdx.x * 4;

    #pragma unroll
    for (int q = 0; q < 4; q++)
        qnS[q * CHN + t] = g_q[(qg0 + q) * CHN + t] + g_qpos[(qg0 + q) * CHN + t];
    __syncthreads();

    // so (256-out) and aw (128-out) GEMMs for 4 queries
    {
        float as[4] = {0.f,0.f,0.f,0.f};
        float aa[4] = {0.f,0.f,0.f,0.f};
        const bool da = (t < 128);
        for (int i = 0; i < CHN; i++) {
            float ws = soW[i * CHN + t];
            float wa = da ? awW[i * 128 + t] : 0.f;
            #pragma unroll
            for (int q = 0; q < 4; q++) {
                float xv = qnS[q * CHN + i];
                as[q] += xv * ws;
                aa[q] += xv * wa;
            }
        }
        float sbv = sob[t];
        #pragma unroll
        for (int q = 0; q < 4; q++) soS[q * CHN + t] = as[q] + sbv;
        if (da) {
            float ab = awb[t];
            #pragma unroll
            for (int q = 0; q < 4; q++) awS[q * 128 + t] = aa[q] + ab;
        }
    }
    __syncthreads();

    // softmax over 16 (frames*pts) per (q, head)
    if (t < 32) {
        int q = t >> 3, h = t & 7;
        float* a = awS + q * 128 + h * 16;
        float m = a[0];
        #pragma unroll
        for (int j = 1; j < 16; j++) m = fmaxf(m, a[j]);
        float ev[16]; float s = 0.f;
        #pragma unroll
        for (int j = 0; j < 16; j++) { ev[j] = expf(a[j] - m); s += ev[j]; }
        float inv = 1.f / s;
        #pragma unroll
        for (int j = 0; j < 16; j++) a[j] = ev[j] * inv;
    }
    __syncthreads();

    // per-query: compute 512 (coef, cell) pairs, then aggregate val vectors
    for (int q = 0; q < 4; q++) {
        int ind = g_ind[qg0 + q];
        int b = (qg0 + q) >> 10;
        if (t < 128) {
            // event t = h*16 + f*4 + p ;  so index 2t (x), 2t+1 (y)
            int f = (t >> 2) & 3;
            float offx = soS[q * CHN + 2 * t];
            float offy = soS[q * CHN + 2 * t + 1];
            float aw = awS[q * 128 + t];
            // xs = rx + offx ; ys = ry + offy  (W=H=128 cancels norm)
            float xs = (float)(ind & 127) + offx;
            float ys = (float)(ind >> 7) + offy;
            float xf = floorf(xs), yf = floorf(ys);
            int x0 = (int)xf, y0 = (int)yf;
            float wx1 = xs - xf, wy1 = ys - yf;
            float wx0 = 1.f - wx1, wy0 = 1.f - wy1;
            int cxs[4] = {x0, x0 + 1, x0, x0 + 1};
            int cys[4] = {y0, y0, y0 + 1, y0 + 1};
            float cw[4] = {wx0 * wy0, wx1 * wy0, wx0 * wy1, wx1 * wy1};
            int base = (b * 4 + f) * HWSZ;
            float evs = 0.f;
            #pragma unroll
            for (int c = 0; c < 4; c++) {
                bool v = (cxs[c] >= 0) & (cxs[c] < 128) & (cys[c] >= 0) & (cys[c] < 128);
                float cf = v ? aw * cw[c] : 0.f;
                evs += cf;
                coefS[4 * t + c] = cf;
                offS[4 * t + c]  = v ? (base + cys[c] * 128 + cxs[c]) * CHN : 0;
            }
            #pragma unroll
            for (int o = 8; o > 0; o >>= 1)
                evs += __shfl_xor_sync(0xffffffffu, evs, o, 16);
            if ((t & 15) == 0) bwAll[q * 8 + (t >> 4)] = evs;
        }
        __syncthreads();
        // aggregation: thread t = channel; per-head register accumulator
        for (int h = 0; h < 8; h++) {
            float acc = 0.f;
            int bb = h * 64;
            #pragma unroll 4
            for (int j = 0; j < 64; j++) {
                float cf = coefS[bb + j];
                if (cf != 0.f) acc += cf * g_val[offS[bb + j] + t];
            }
            aggS[(q * 8 + h) * CHN + t] = acc;
        }
        __syncthreads();
    }

    // vp projection for all 4 queries (weights read once per block)
    {
        int h = t >> 5;
        float acc[4] = {0.f,0.f,0.f,0.f};
        for (int i = 0; i < CHN; i++) {
            float wv = vpW[i * CHN + t];
            #pragma unroll
            for (int q = 0; q < 4; q++) acc[q] += aggS[(q * 8 + h) * CHN + i] * wv;
        }
        float vb = vpb[t];
        #pragma unroll
        for (int q = 0; q < 4; q++)
            g_attn[(qg0 + q) * CHN + t] = acc[q] + bwAll[q * 8 + h] * vb;
    }
}

// ---------------- K5: per-layer tail: op-proj + LN1 + FFN + LN2 ----------------
__device__ __forceinline__ void ln16(float v[16], float* redA, float* redB,
                                     float* mu, float* rs,
                                     const float* g, const float* b, int t) {
    int w = t >> 5, ln = t & 31;
    #pragma unroll
    for (int q = 0; q < 16; q++) {
        float s = v[q], s2 = v[q] * v[q];
        #pragma unroll
        for (int o = 16; o > 0; o >>= 1) {
            s  += __shfl_xor_sync(0xffffffffu, s, o);
            s2 += __shfl_xor_sync(0xffffffffu, s2, o);
        }
        if (ln == 0) { redA[q * 8 + w] = s; redB[q * 8 + w] = s2; }
    }
    __syncthreads();
    if (t < 16) {
        float s = 0.f, s2 = 0.f;
        #pragma unroll
        for (int k = 0; k < 8; k++) { s += redA[t * 8 + k]; s2 += redB[t * 8 + k]; }
        float m = s * (1.f / 256.f);
        mu[t] = m;
        rs[t] = rsqrtf(s2 * (1.f / 256.f) - m * m + 1e-5f);
    }
    __syncthreads();
    float gg = g[t], bb = b[t];
    #pragma unroll
    for (int q = 0; q < 16; q++) v[q] = (v[q] - mu[q]) * rs[q] * gg + bb;
}

__global__ __launch_bounds__(256) void k_tail(
    const float* __restrict__ opW, const float* __restrict__ opb,
    const float* __restrict__ g1, const float* __restrict__ b1,
    const float* __restrict__ W1, const float* __restrict__ fb1,
    const float* __restrict__ W2, const float* __restrict__ fb2,
    const float* __restrict__ g2, const float* __restrict__ b2) {
    __shared__ float qS[16 * CHN];    // LN1 output (FFN input + residual source)
    __shared__ float buf[16 * CHN];   // attn, then hidden chunks
    __shared__ float redA[16 * 8], redB[16 * 8];
    __shared__ float mu[16], rs[16];
    int t = threadIdx.x;
    int qg0 = blockIdx.x * 16;

    float v[16];
    #pragma unroll
    for (int q = 0; q < 16; q++) {
        v[q] = g_q[(qg0 + q) * CHN + t];
        buf[q * CHN + t] = g_attn[(qg0 + q) * CHN + t];
    }
    __syncthreads();

    // q += attn @ opW + opb
    {
        float acc[16];
        #pragma unroll
        for (int q = 0; q < 16; q++) acc[q] = 0.f;
        for (int i = 0; i < CHN; i++) {
            float wv = opW[i * CHN + t];
            #pragma unroll
            for (int q = 0; q < 16; q++) acc[q] += buf[q * CHN + i] * wv;
        }
        float ob = opb[t];
        #pragma unroll
        for (int q = 0; q < 16; q++) v[q] += acc[q] + ob;
    }
    __syncthreads();   // buf reuse below

    // LN1
    ln16(v, redA, redB, mu, rs, g1, b1, t);
    #pragma unroll
    for (int q = 0; q < 16; q++) qS[q * CHN + t] = v[q];
    __syncthreads();

    // FFN 256 -> 1024 (relu) -> 256, hidden in 4 chunks of 256
    float oacc[16];
    #pragma unroll
    for (int q = 0; q < 16; q++) oacc[q] = 0.f;
    for (int chunk = 0; chunk < 4; chunk++) {
        float h[16];
        #pragma unroll
        for (int q = 0; q < 16; q++) h[q] = 0.f;
        int j = chunk * CHN + t;
        for (int i = 0; i < CHN; i++) {
            float wv = W1[i * 1024 + j];
            #pragma unroll
            for (int q = 0; q < 16; q++) h[q] += qS[q * CHN + i] * wv;
        }
        float bj = fb1[j];
        #pragma unroll
        for (int q = 0; q < 16; q++) buf[q * CHN + t] = fmaxf(h[q] + bj, 0.f);
        __syncthreads();
        for (int i = 0; i < CHN; i++) {
            float wv = W2[(chunk * CHN + i) * CHN + t];
            #pragma unroll
            for (int q = 0; q < 16; q++) oacc[q] += buf[q * CHN + i] * wv;
        }
        __syncthreads();
    }
    float fb = fb2[t];
    #pragma unroll
    for (int q = 0; q < 16; q++) v[q] = qS[q * CHN + t] + oacc[q] + fb;

    // LN2
    ln16(v, redA, redB, mu, rs, g2, b2, t);
    #pragma unroll
    for (int q = 0; q < 16; q++) g_q[(qg0 + q) * CHN + t] = v[q];
}

// ---------------- K6/K7: zero-fill output, scatter queries ----------------
__global__ void k_zero(float4* __restrict__ out) {
    out[(size_t)blockIdx.x * 256 + threadIdx.x] = make_float4(0.f, 0.f, 0.f, 0.f);
}

__global__ void k_scatter(float* __restrict__ out) {
    int k = blockIdx.x, t = threadIdx.x;
    int b = k >> 10;
    int ind = g_ind[k];
    out[(b * CHN + t) * HWSZ + ind] = g_q[k * CHN + t];
}

// ---------------- launch ----------------
extern "C" void kernel_launch(void* const* d_in, const int* in_sizes, int n_in,
                              void* d_out, int out_size) {
    const float* x    = (const float*)d_in[0];
    const float* preds= (const float*)d_in[1];
    const float* hm   = (const float*)d_in[2];
    const float* mW1  = (const float*)d_in[3];
    const float* mb1  = (const float*)d_in[4];
    const float* mW2  = (const float*)d_in[5];
    const float* mb2  = (const float*)d_in[6];
    const float* tp   = (const float*)d_in[7];
    const float* rowe = (const float*)d_in[8];
    const float* cole = (const float*)d_in[9];
    const float* soW  = (const float*)d_in[10];
    const float* sob  = (const float*)d_in[11];
    const float* awW  = (const float*)d_in[12];
    const float* awb  = (const float*)d_in[13];
    const float* vpW  = (const float*)d_in[14];
    const float* vpb  = (const float*)d_in[15];
    const float* opW  = (const float*)d_in[16];
    const float* opb  = (const float*)d_in[17];
    const float* l1g  = (const float*)d_in[18];
    const float* l1b  = (const float*)d_in[19];
    const float* fW1  = (const float*)d_in[20];
    const float* fb1  = (const float*)d_in[21];
    const float* fW2  = (const float*)d_in[22];
    const float* fb2  = (const float*)d_in[23];
    const float* l2g  = (const float*)d_in[24];
    const float* l2b  = (const float*)d_in[25];
    float* out = (float*)d_out;

    k_transpose<<<dim3(4, 8, 1024), dim3(32, 32)>>>(x, tp);
    k_topk<<<2, 1024>>>(hm);
    k_qinit<<<256, 256>>>(preds, mW1, mb1, mW2, mb2, rowe, cole);
    for (int l = 0; l < 3; l++) {
        k_sample<<<512, 256>>>(soW + l * 65536, sob + l * 256,
                               awW + l * 32768, awb + l * 128,
                               vpW + l * 65536, vpb + l * 256);
        k_tail<<<128, 256>>>(opW + l * 65536, opb + l * 256,
                             l1g + l * 256, l1b + l * 256,
                             fW1 + l * 262144, fb1 + l * 1024,
                             fW2 + l * 262144, fb2 + l * 256,
                             l2g + l * 256, l2b + l * 256);
    }
    k_zero<<<8192, 256>>>((float4*)out);
    k_scatter<<<2048, 256>>>(out);
}

// round 3
// speedup vs baseline: 1.3908x; 1.3908x over previous
#include <cuda_runtime.h>
#include <math.h>

#define HWSZ 16384
#define CHN  256
#define KQ   1024
#define NQ   2048
#define HSLOTS 512

// ---------------- device scratch (static, allocation-free) ----------------
__device__ float    g_val[(size_t)2 * 4 * HWSZ * CHN];   // [b*4+f][y][x][c], +time_pos
__device__ unsigned g_keys[2 * HWSZ];
__device__ int      g_ind[NQ];
__device__ float    g_q[NQ * CHN];
__device__ float    g_qpos[NQ * CHN];
__device__ float    g_attn[NQ * CHN];

__device__ __forceinline__ float gelu_tanh(float v) {
    float c = 0.7978845608028654f * (v + 0.044715f * v * v * v);
    return 0.5f * v * (1.0f + tanhf(c));
}

// ---------------- K1: transpose x[b,f,c,y,x] -> g_val[b,f,y,x,c] (+time_pos) ----------------
__global__ void k_transpose(const float* __restrict__ x, const float* __restrict__ tp) {
    __shared__ float tile[32][33];
    int xt = blockIdx.x * 32;
    int ct = blockIdx.y * 32;
    int z  = blockIdx.z;
    int y  = z & 127;
    int bf = z >> 7;
    int f  = bf & 3;
    int tx = threadIdx.x, ty = threadIdx.y;
    tile[ty][tx] = x[((size_t)(bf * CHN + ct + ty) * 128 + y) * 128 + xt + tx];
    __syncthreads();
    g_val[((size_t)(bf * 128 + y) * 128 + xt + ty) * CHN + ct + tx] =
        tile[tx][ty] + tp[f * CHN + ct + tx];
}

// ---------------- K2: channel-max score + radix top-1024 per batch ----------------
__global__ __launch_bounds__(1024) void k_topk(const float* __restrict__ hm) {
    int b = blockIdx.x, t = threadIdx.x;
    __shared__ unsigned hist[256];
    __shared__ unsigned sh[4];
    const float* hb = hm + (size_t)b * 10 * HWSZ;

    for (int i = t; i < HWSZ; i += 1024) {
        float m = hb[i];
        #pragma unroll
        for (int c = 1; c < 10; c++) m = fmaxf(m, hb[c * HWSZ + i]);
        unsigned u = __float_as_uint(m);
        u = (u & 0x80000000u) ? ~u : (u | 0x80000000u);
        g_keys[b * HWSZ + i] = u;
    }
    __syncthreads();

    unsigned prefix = 0, r = KQ;
    for (int byte = 3; byte >= 0; byte--) {
        if (t < 256) hist[t] = 0;
        __syncthreads();
        int sh8 = byte * 8;
        unsigned pm = (byte == 3) ? 0u : (0xFFFFFFFFu << (8 * (byte + 1)));
        for (int i = t; i < HWSZ; i += 1024) {
            unsigned k = g_keys[b * HWSZ + i];
            if ((k & pm) == (prefix & pm)) atomicAdd(&hist[(k >> sh8) & 255u], 1u);
        }
        __syncthreads();
        if (t == 0) {
            unsigned cum = 0, d = 0;
            for (int dd = 255; dd >= 0; dd--) {
                if (cum + hist[dd] >= r) { d = (unsigned)dd; break; }
                cum += hist[dd];
            }
            sh[0] = d; sh[1] = r - cum;
        }
        __syncthreads();
        prefix |= sh[0] << sh8;
        r = sh[1];
        __syncthreads();
    }
    unsigned T = prefix;
    if (t == 0) { sh[2] = 0; sh[3] = 0; }
    __syncthreads();
    for (int i = t; i < HWSZ; i += 1024)
        if (g_keys[b * HWSZ + i] > T) atomicAdd(&sh[2], 1u);
    __syncthreads();
    unsigned cgt = sh[2];
    unsigned neq = KQ - cgt;
    __syncthreads();
    if (t == 0) sh[2] = 0;
    __syncthreads();
    for (int i = t; i < HWSZ; i += 1024) {
        unsigned k = g_keys[b * HWSZ + i];
        if (k > T) {
            unsigned s = atomicAdd(&sh[2], 1u);
            g_ind[b * KQ + s] = i;
        } else if (k == T) {
            unsigned e = atomicAdd(&sh[3], 1u);
            if (e < neq) g_ind[b * KQ + cgt + e] = i;
        }
    }
}

// ---------------- K3: query-init MLP + positional embed gather ----------------
__global__ __launch_bounds__(256) void k_qinit(
    const float* __restrict__ preds,
    const float* __restrict__ W1, const float* __restrict__ b1,
    const float* __restrict__ W2, const float* __restrict__ b2,
    const float* __restrict__ rowe, const float* __restrict__ cole) {
    __shared__ float q0S[8][70];
    __shared__ float hidS[8][CHN];
    __shared__ int   indS[8];
    int t = threadIdx.x;
    int qg0 = blockIdx.x * 8;
    if (t < 8) indS[t] = g_ind[qg0 + t];
    __syncthreads();
    for (int idx = t; idx < 8 * 70; idx += 256) {
        int q = idx / 70, j = idx - q * 70;
        int b = (qg0 + q) >> 10;
        q0S[q][j] = preds[(b * 70 + j) * HWSZ + indS[q]];
    }
    #pragma unroll
    for (int q = 0; q < 8; q++) {
        int ind = indS[q];
        int xx = ind & 127, yy = ind >> 7;
        float pv = (t < 128) ? cole[xx * 128 + t] : rowe[yy * 128 + (t - 128)];
        g_qpos[(qg0 + q) * CHN + t] = pv;
    }
    __syncthreads();
    float acc[8] = {0.f,0.f,0.f,0.f,0.f,0.f,0.f,0.f};
    for (int j = 0; j < 70; j++) {
        float w = W1[j * CHN + t];
        #pragma unroll
        for (int q = 0; q < 8; q++) acc[q] += q0S[q][j] * w;
    }
    float bb = b1[t];
    #pragma unroll
    for (int q = 0; q < 8; q++) hidS[q][t] = gelu_tanh(acc[q] + bb);
    __syncthreads();
    float a2[8] = {0.f,0.f,0.f,0.f,0.f,0.f,0.f,0.f};
    for (int i = 0; i < CHN; i++) {
        float w = W2[i * CHN + t];
        #pragma unroll
        for (int q = 0; q < 8; q++) a2[q] += hidS[q][i] * w;
    }
    float b2v = b2[t];
    #pragma unroll
    for (int q = 0; q < 8; q++) g_q[(qg0 + q) * CHN + t] = a2[q] + b2v;
}

// ---------------- K4: per-layer sampling attention (dedup hash version) ----------------
// dynamic smem layout (floats):
//   aggS   [0, 8192)       4q x 8h x 256ch  (first 1024 aliased as qnS)
//   soS    [8192, 9216)
//   awS    [9216, 9728)
//   hcoef  [9728, 13824)   512 slots x 8 heads
//   hkey   [13824, 14336)  (int)
//   list   [14336, 14848)  (int)
//   bwAll  [14848, 14880)
//   cnt    [14880]         (int)
#define SMP_WORDS 14896
__global__ __launch_bounds__(256) void k_sample(
    const float* __restrict__ soW, const float* __restrict__ sob,
    const float* __restrict__ awW, const float* __restrict__ awb,
    const float* __restrict__ vpW, const float* __restrict__ vpb) {
    extern __shared__ float sm[];
    float* aggS  = sm;
    float* qnS   = sm;                 // alias: dead before aggS writes begin
    float* soS   = sm + 8192;
    float* awS   = sm + 9216;
    float* hcoef = sm + 9728;
    int*   hkey  = (int*)(sm + 13824);
    int*   list  = (int*)(sm + 14336);
    float* bwAll = sm + 14848;
    int*   cntS  = (int*)(sm + 14880);

    int t = threadIdx.x;
    int qg0 = blockIdx.x * 4;

    #pragma unroll
    for (int q = 0; q < 4; q++)
        qnS[q * CHN + t] = g_q[(qg0 + q) * CHN + t] + g_qpos[(qg0 + q) * CHN + t];
    __syncthreads();

    // so (256-out) and aw (128-out) GEMMs for 4 queries
    {
        float as[4] = {0.f,0.f,0.f,0.f};
        float aa[4] = {0.f,0.f,0.f,0.f};
        const bool da = (t < 128);
        for (int i = 0; i < CHN; i++) {
            float ws = soW[i * CHN + t];
            float wa = da ? awW[i * 128 + t] : 0.f;
            #pragma unroll
            for (int q = 0; q < 4; q++) {
                float xv = qnS[q * CHN + i];
                as[q] += xv * ws;
                aa[q] += xv * wa;
            }
        }
        float sbv = sob[t];
        #pragma unroll
        for (int q = 0; q < 4; q++) soS[q * CHN + t] = as[q] + sbv;
        if (da) {
            float ab = awb[t];
            #pragma unroll
            for (int q = 0; q < 4; q++) awS[q * 128 + t] = aa[q] + ab;
        }
    }
    __syncthreads();

    // softmax over 16 (frames*pts) per (q, head)
    if (t < 32) {
        int q = t >> 3, h = t & 7;
        float* a = awS + q * 128 + h * 16;
        float m = a[0];
        #pragma unroll
        for (int j = 1; j < 16; j++) m = fmaxf(m, a[j]);
        float ev[16]; float s = 0.f;
        #pragma unroll
        for (int j = 0; j < 16; j++) { ev[j] = expf(a[j] - m); s += ev[j]; }
        float inv = 1.f / s;
        #pragma unroll
        for (int j = 0; j < 16; j++) a[j] = ev[j] * inv;
    }
    __syncthreads();

    // per-query: hash-dedup corner contributions, then aggregate distinct cells
    for (int q = 0; q < 4; q++) {
        // clear hash
        hkey[t] = -1; hkey[t + 256] = -1;
        #pragma unroll
        for (int k = 0; k < 16; k++) hcoef[k * 256 + t] = 0.f;
        if (t == 0) *cntS = 0;
        __syncthreads();

        int ind = g_ind[qg0 + q];
        int b = (qg0 + q) >> 10;
        if (t < 128) {
            int h = t >> 4;
            int f = (t >> 2) & 3;
            float offx = soS[q * CHN + 2 * t];
            float offy = soS[q * CHN + 2 * t + 1];
            float aw = awS[q * 128 + t];
            float xs = (float)(ind & 127) + offx;
            float ys = (float)(ind >> 7) + offy;
            float xf = floorf(xs), yf = floorf(ys);
            int x0 = (int)xf, y0 = (int)yf;
            float wx1 = xs - xf, wy1 = ys - yf;
            float wx0 = 1.f - wx1, wy0 = 1.f - wy1;
            int cxs[4] = {x0, x0 + 1, x0, x0 + 1};
            int cys[4] = {y0, y0, y0 + 1, y0 + 1};
            float cw[4] = {wx0 * wy0, wx1 * wy0, wx0 * wy1, wx1 * wy1};
            int base = (b * 4 + f) * HWSZ;
            #pragma unroll
            for (int c = 0; c < 4; c++) {
                bool v = (cxs[c] >= 0) & (cxs[c] < 128) & (cys[c] >= 0) & (cys[c] < 128);
                if (v) {
                    int key = base + cys[c] * 128 + cxs[c];
                    float cf = aw * cw[c];
                    unsigned s = ((unsigned)key * 2654435761u) >> 19;
                    s &= (HSLOTS - 1);
                    while (true) {
                        int prev = atomicCAS(&hkey[s], -1, key);
                        if (prev == -1 || prev == key) break;
                        s = (s + 1) & (HSLOTS - 1);
                    }
                    atomicAdd(&hcoef[s * 8 + h], cf);
                }
            }
        }
        __syncthreads();
        // compact occupied slots
        for (int s = t; s < HSLOTS; s += 256)
            if (hkey[s] >= 0) {
                int pos = atomicAdd(cntS, 1);
                list[pos] = s;
            }
        __syncthreads();
        int D = *cntS;
        // aggregate: thread t = channel
        float acc[8] = {0.f,0.f,0.f,0.f,0.f,0.f,0.f,0.f};
        for (int d = 0; d < D; d++) {
            int slot = list[d];
            int cell = hkey[slot];
            float v = __ldg(&g_val[(size_t)cell * CHN + t]);
            const float* wv = hcoef + slot * 8;
            #pragma unroll
            for (int h = 0; h < 8; h++) acc[h] += wv[h] * v;
        }
        #pragma unroll
        for (int h = 0; h < 8; h++) aggS[(q * 8 + h) * CHN + t] = acc[h];
        if (t < 8) {
            float s = 0.f;
            for (int d = 0; d < D; d++) s += hcoef[list[d] * 8 + t];
            bwAll[q * 8 + t] = s;
        }
        __syncthreads();
    }

    // vp projection for all 4 queries (weights read once per block)
    {
        int h = t >> 5;
        float acc[4] = {0.f,0.f,0.f,0.f};
        for (int i4 = 0; i4 < 64; i4++) {
            float w0 = vpW[(4 * i4 + 0) * CHN + t];
            float w1 = vpW[(4 * i4 + 1) * CHN + t];
            float w2 = vpW[(4 * i4 + 2) * CHN + t];
            float w3 = vpW[(4 * i4 + 3) * CHN + t];
            #pragma unroll
            for (int q = 0; q < 4; q++) {
                const float4 a = ((const float4*)(aggS + (q * 8 + h) * CHN))[i4];
                acc[q] += a.x * w0 + a.y * w1 + a.z * w2 + a.w * w3;
            }
        }
        float vb = vpb[t];
        #pragma unroll
        for (int q = 0; q < 4; q++)
            g_attn[(qg0 + q) * CHN + t] = acc[q] + bwAll[q * 8 + h] * vb;
    }
}

// ---------------- K5: per-layer tail: op-proj + LN1 + FFN + LN2 (Q=8) ----------------
__device__ __forceinline__ void ln8(float v[8], float* redA, float* redB,
                                    float* mu, float* rs,
                                    const float* g, const float* b, int t) {
    int w = t >> 5, ln = t & 31;
    #pragma unroll
    for (int q = 0; q < 8; q++) {
        float s = v[q], s2 = v[q] * v[q];
        #pragma unroll
        for (int o = 16; o > 0; o >>= 1) {
            s  += __shfl_xor_sync(0xffffffffu, s, o);
            s2 += __shfl_xor_sync(0xffffffffu, s2, o);
        }
        if (ln == 0) { redA[q * 8 + w] = s; redB[q * 8 + w] = s2; }
    }
    __syncthreads();
    if (t < 8) {
        float s = 0.f, s2 = 0.f;
        #pragma unroll
        for (int k = 0; k < 8; k++) { s += redA[t * 8 + k]; s2 += redB[t * 8 + k]; }
        float m = s * (1.f / 256.f);
        mu[t] = m;
        rs[t] = rsqrtf(s2 * (1.f / 256.f) - m * m + 1e-5f);
    }
    __syncthreads();
    float gg = g[t], bb = b[t];
    #pragma unroll
    for (int q = 0; q < 8; q++) v[q] = (v[q] - mu[q]) * rs[q] * gg + bb;
}

__global__ __launch_bounds__(256) void k_tail(
    const float* __restrict__ opW, const float* __restrict__ opb,
    const float* __restrict__ g1, const float* __restrict__ b1,
    const float* __restrict__ W1, const float* __restrict__ fb1,
    const float* __restrict__ W2, const float* __restrict__ fb2,
    const float* __restrict__ g2, const float* __restrict__ b2) {
    __shared__ float qS[8 * CHN];
    __shared__ float buf[8 * CHN];
    __shared__ float redA[8 * 8], redB[8 * 8];
    __shared__ float mu[8], rs[8];
    int t = threadIdx.x;
    int qg0 = blockIdx.x * 8;

    float v[8];
    #pragma unroll
    for (int q = 0; q < 8; q++) {
        v[q] = g_q[(qg0 + q) * CHN + t];
        buf[q * CHN + t] = g_attn[(qg0 + q) * CHN + t];
    }
    __syncthreads();

    // q += attn @ opW + opb  (accumulate straight into v)
    for (int i4 = 0; i4 < 64; i4++) {
        float w0 = opW[(4 * i4 + 0) * CHN + t];
        float w1 = opW[(4 * i4 + 1) * CHN + t];
        float w2 = opW[(4 * i4 + 2) * CHN + t];
        float w3 = opW[(4 * i4 + 3) * CHN + t];
        #pragma unroll
        for (int q = 0; q < 8; q++) {
            const float4 a = ((const float4*)(buf + q * CHN))[i4];
            v[q] += a.x * w0 + a.y * w1 + a.z * w2 + a.w * w3;
        }
    }
    {
        float ob = opb[t];
        #pragma unroll
        for (int q = 0; q < 8; q++) v[q] += ob;
    }
    __syncthreads();   // buf reused for hidden chunks

    // LN1
    ln8(v, redA, redB, mu, rs, g1, b1, t);
    #pragma unroll
    for (int q = 0; q < 8; q++) qS[q * CHN + t] = v[q];
    __syncthreads();

    // FFN 256 -> 1024 (relu) -> 256 in 4 hidden chunks; accumulate into v
    for (int chunk = 0; chunk < 4; chunk++) {
        float h[8] = {0.f,0.f,0.f,0.f,0.f,0.f,0.f,0.f};
        int j = chunk * CHN + t;
        for (int i4 = 0; i4 < 64; i4++) {
            float w0 = W1[(4 * i4 + 0) * 1024 + j];
            float w1 = W1[(4 * i4 + 1) * 1024 + j];
            float w2 = W1[(4 * i4 + 2) * 1024 + j];
            float w3 = W1[(4 * i4 + 3) * 1024 + j];
            #pragma unroll
            for (int q = 0; q < 8; q++) {
                const float4 a = ((const float4*)(qS + q * CHN))[i4];
                h[q] += a.x * w0 + a.y * w1 + a.z * w2 + a.w * w3;
            }
        }
        float bj = fb1[j];
        #pragma unroll
        for (int q = 0; q < 8; q++) buf[q * CHN + t] = fmaxf(h[q] + bj, 0.f);
        __syncthreads();
        for (int i4 = 0; i4 < 64; i4++) {
            float w0 = W2[(chunk * CHN + 4 * i4 + 0) * CHN + t];
            float w1 = W2[(chunk * CHN + 4 * i4 + 1) * CHN + t];
            float w2 = W2[(chunk * CHN + 4 * i4 + 2) * CHN + t];
            float w3 = W2[(chunk * CHN + 4 * i4 + 3) * CHN + t];
            #pragma unroll
            for (int q = 0; q < 8; q++) {
                const float4 a = ((const float4*)(buf + q * CHN))[i4];
                v[q] += a.x * w0 + a.y * w1 + a.z * w2 + a.w * w3;
            }
        }
        __syncthreads();
    }
    {
        float fb = fb2[t];
        #pragma unroll
        for (int q = 0; q < 8; q++) v[q] += fb;
    }

    // LN2
    ln8(v, redA, redB, mu, rs, g2, b2, t);
    #pragma unroll
    for (int q = 0; q < 8; q++) g_q[(qg0 + q) * CHN + t] = v[q];
}

// ---------------- K6/K7: zero-fill output, scatter queries ----------------
__global__ void k_zero(float4* __restrict__ out) {
    out[(size_t)blockIdx.x * 256 + threadIdx.x] = make_float4(0.f, 0.f, 0.f, 0.f);
}

__global__ void k_scatter(float* __restrict__ out) {
    int k = blockIdx.x, t = threadIdx.x;
    int b = k >> 10;
    int ind = g_ind[k];
    out[(b * CHN + t) * HWSZ + ind] = g_q[k * CHN + t];
}

// ---------------- launch ----------------
extern "C" void kernel_launch(void* const* d_in, const int* in_sizes, int n_in,
                              void* d_out, int out_size) {
    const float* x    = (const float*)d_in[0];
    const float* preds= (const float*)d_in[1];
    const float* hm   = (const float*)d_in[2];
    const float* mW1  = (const float*)d_in[3];
    const float* mb1  = (const float*)d_in[4];
    const float* mW2  = (const float*)d_in[5];
    const float* mb2  = (const float*)d_in[6];
    const float* tp   = (const float*)d_in[7];
    const float* rowe = (const float*)d_in[8];
    const float* cole = (const float*)d_in[9];
    const float* soW  = (const float*)d_in[10];
    const float* sob  = (const float*)d_in[11];
    const float* awW  = (const float*)d_in[12];
    const float* awb  = (const float*)d_in[13];
    const float* vpW  = (const float*)d_in[14];
    const float* vpb  = (const float*)d_in[15];
    const float* opW  = (const float*)d_in[16];
    const float* opb  = (const float*)d_in[17];
    const float* l1g  = (const float*)d_in[18];
    const float* l1b  = (const float*)d_in[19];
    const float* fW1  = (const float*)d_in[20];
    const float* fb1  = (const float*)d_in[21];
    const float* fW2  = (const float*)d_in[22];
    const float* fb2  = (const float*)d_in[23];
    const float* l2g  = (const float*)d_in[24];
    const float* l2b  = (const float*)d_in[25];
    float* out = (float*)d_out;

    static int smp_smem_set = 0;
    const int smp_bytes = SMP_WORDS * 4;
    if (!smp_smem_set) {
        cudaFuncSetAttribute(k_sample, cudaFuncAttributeMaxDynamicSharedMemorySize, smp_bytes);
        smp_smem_set = 1;
    }

    k_transpose<<<dim3(4, 8, 1024), dim3(32, 32)>>>(x, tp);
    k_topk<<<2, 1024>>>(hm);
    k_qinit<<<256, 256>>>(preds, mW1, mb1, mW2, mb2, rowe, cole);
    for (int l = 0; l < 3; l++) {
        k_sample<<<512, 256, smp_bytes>>>(soW + l * 65536, sob + l * 256,
                                          awW + l * 32768, awb + l * 128,
                                          vpW + l * 65536, vpb + l * 256);
        k_tail<<<256, 256>>>(opW + l * 65536, opb + l * 256,
                             l1g + l * 256, l1b + l * 256,
                             fW1 + l * 262144, fb1 + l * 1024,
                             fW2 + l * 262144, fb2 + l * 256,
                             l2g + l * 256, l2b + l * 256);
    }
    k_zero<<<8192, 256>>>((float4*)out);
    k_scatter<<<2048, 256>>>(out);
}